// round 13
// baseline (speedup 1.0000x reference)
#include <cuda_runtime.h>
#include <cuda_fp16.h>

// Problem constants
#define G_   64
#define N_   2048
#define E_   16384
#define GE_  (G_ * E_)          // 1048576 edges total
#define NV_  2047               // nodes per graph excluding center
#define F_   128
#define GN_  (G_ * N_)          // 131072 node slots
#define CAP_ 64                 // per-node in-edge capacity (P(overflow) ~ 1e-35)

// ---------------- device scratch ----------------
// per node: 256 fp16 = [dis*xc (128) | dis*xr (128)]  (512 B/row)
__device__ __half g_h[(size_t)GN_ * 256];
__device__ float g_z[2048 * 256];            // per-v accum: [core(128) | red(128)]
__device__ int   g_cnt[GN_];
__device__ int   g_col[(size_t)GN_ * CAP_];  // local src ids
__device__ float g_dis[GN_];
__device__ float g_cterm[G_ * F_];
__device__ int   g_is64;
__device__ float g_wt[128 * 128];            // W^T of Wm bottom half: wt[c][k]

// ---------------- packed f32x2 helpers (sm_103a) ----------------
__device__ __forceinline__ unsigned long long fma2(unsigned long long a,
                                                   unsigned long long b,
                                                   unsigned long long c) {
    unsigned long long d;
    asm("fma.rn.f32x2 %0, %1, %2, %3;" : "=l"(d) : "l"(a), "l"(b), "l"(c));
    return d;
}
__device__ __forceinline__ unsigned long long pack2(float x) {
    unsigned long long d;
    asm("mov.b64 %0, {%1, %2};" : "=l"(d) : "f"(x), "f"(x));
    return d;
}
__device__ __forceinline__ void unpack2(unsigned long long v, float& lo, float& hi) {
    asm("mov.b64 {%0, %1}, %2;" : "=f"(lo), "=f"(hi) : "l"(v));
}
__device__ __forceinline__ void red4(float* p, float a, float b, float c, float d) {
    asm volatile("red.global.add.v4.f32 [%0], {%1, %2, %3, %4};"
                 :: "l"(p), "f"(a), "f"(b), "f"(c), "f"(d) : "memory");
}
__device__ __forceinline__ int edge_val(const void* ei, long idx) {
    if (g_is64) return (int)((const long long*)ei)[idx];
    return ((const int*)ei)[idx];
}
__device__ __forceinline__ void h8_to_f8(uint4 t, float* f) {
    float2 p;
    p = __half22float2(*(__half2*)&t.x); f[0] = p.x; f[1] = p.y;
    p = __half22float2(*(__half2*)&t.y); f[2] = p.x; f[3] = p.y;
    p = __half22float2(*(__half2*)&t.z); f[4] = p.x; f[5] = p.y;
    p = __half22float2(*(__half2*)&t.w); f[6] = p.x; f[7] = p.y;
}

// ---------------- init: dtype detect + zero cnt/z + W^T build ------------
__global__ void k_init(const void* cni, const float* __restrict__ Wm) {
    int i = blockIdx.x * blockDim.x + threadIdx.x;
    if (i == 0) g_is64 = (((const int*)cni)[1] == 0) ? 1 : 0;
    if (i < GN_) g_cnt[i] = 0;
    g_z[i] = 0.0f;                     // grid is exactly 2048*256 = |g_z|
    if (i < 16384) {                   // wt[c][k] = Wm[128+k][c]
        int c = i >> 7, k = i & 127;
        g_wt[c * 128 + k] = Wm[(128 + k) * 128 + c];
    }
}

// one pass: bucketed edge build
__global__ void k_build(const void* ei) {
    int e = blockIdx.x * blockDim.x + threadIdx.x;
    if (e < GE_) {
        int d = edge_val(ei, (long)GE_ + e);
        int s = edge_val(ei, e) & (N_ - 1);
        int slot = atomicAdd(&g_cnt[d], 1);
        if (slot < CAP_) g_col[(long)d * CAP_ + slot] = s;
    }
}

// merged: blocks [0,64) compute ce/cterm; blocks [64,320) compute g_dis
__global__ void __launch_bounds__(512)
k_ce_dis(const float* __restrict__ x, const void* cni,
         const float* __restrict__ W1, const float* __restrict__ b1,
         const float* __restrict__ Wm, const float* __restrict__ bm) {
    if (blockIdx.x >= 64) {
        int i = (blockIdx.x - 64) * 512 + threadIdx.x;
        if (i < GN_) g_dis[i] = rsqrtf(1.0f + (float)g_cnt[i]);
        return;
    }
    __shared__ float sx[128], sp[4][128], sce[128];
    int g = blockIdx.x, tid = threadIdx.x;
    int col = tid & 127, seg = tid >> 7;
    long center;
    if (g_is64) center = ((const long long*)cni)[g];
    else        center = ((const int*)cni)[g];
    if (tid < 128) sx[tid] = x[((long)g * N_ + center) * F_ + tid];
    __syncthreads();

    float s = 0.f;
    int k0 = seg * 32;
    #pragma unroll 32
    for (int k = 0; k < 32; k++) s += sx[k0 + k] * W1[(k0 + k) * 128 + col];
    sp[seg][col] = s;
    __syncthreads();
    if (seg == 0) sce[col] = b1[col] + sp[0][col] + sp[1][col] + sp[2][col] + sp[3][col];
    __syncthreads();

    float t = 0.f;
    #pragma unroll 32
    for (int k = 0; k < 32; k++) t += sce[k0 + k] * Wm[(k0 + k) * 128 + col];
    sp[seg][col] = t;
    __syncthreads();
    if (seg == 0)
        g_cterm[g * 128 + col] = bm[col] + sp[0][col] + sp[1][col] + sp[2][col] + sp[3][col];
}

// ---------------- mask GEMM: f32x2 K-pair, 64-row tiles, 2 CTA/SM --------
// Block 64x128, 512 threads, __launch_bounds__(512,2) -> <=64 regs.
// tx = tid&31 (col lane), ty = tid>>5 (0..15). Thread: rows ty*4..+3,
// cols tx+32j (j=0..3). acc[i][j] f32x2 = (even-k, odd-k) partials.
// A: xs[r*130+k] LDS.64 broadcast. B: wt[c*130+k] LDS.64 conflict-free.
#define SRX 130
#define XS_OFF 0                       // 64*130*4  = 33280
#define WT_OFF 33280                   // 128*130*4 = 66560
#define CTS_OFF 99840                  // 512
#define DIS_OFF 100352                 // 256
#define SMEM_MASK_TOTAL 100608
// staged fp16 epilogue reuses WT region: 64 rows x 260 halfs = 33280 B

__global__ void __launch_bounds__(512, 2)
k_mask(const float* __restrict__ x) {
    extern __shared__ char smem[];
    float* xs = (float*)(smem + XS_OFF);
    float* wt = (float*)(smem + WT_OFF);
    float* cts = (float*)(smem + CTS_OFF);
    float* dss = (float*)(smem + DIS_OFF);

    const int tid = threadIdx.x;
    const int g = blockIdx.y, vb = blockIdx.x;
    const int node0 = g * N_ + vb * 64;

    // fill xs (64-row x tile) with 8B stores
    {
        const float2* xg = (const float2*)(x + (long)node0 * F_);
        #pragma unroll
        for (int i = tid; i < 4096; i += 512) {
            int r = i >> 6, c2 = (i & 63) * 2;
            *(float2*)&xs[r * SRX + c2] = xg[i];
        }
    }
    // fill wt (full 128x128 W^T)
    {
        const float2* wg = (const float2*)g_wt;
        #pragma unroll
        for (int i = tid; i < 8192; i += 512) {
            int r = i >> 6, c2 = (i & 63) * 2;
            *(float2*)&wt[r * SRX + c2] = wg[i];
        }
    }
    if (tid < 128) cts[tid] = g_cterm[g * 128 + tid];
    if (tid < 64)  dss[tid] = g_dis[node0 + tid];
    __syncthreads();

    const int tx = tid & 31, ty = tid >> 5;
    const int r0 = ty * 4;

    unsigned long long acc[4][4];
    #pragma unroll
    for (int i = 0; i < 4; i++)
        #pragma unroll
        for (int j = 0; j < 4; j++) acc[i][j] = 0ull;

    const float* xrow = xs + r0 * SRX;
    const float* wcol = wt + tx * SRX;

    #pragma unroll 2
    for (int kp = 0; kp < 64; kp++) {
        const int k = 2 * kp;
        unsigned long long b0 = *(const unsigned long long*)&wcol[k];
        unsigned long long b1 = *(const unsigned long long*)&wcol[32 * SRX + k];
        unsigned long long b2 = *(const unsigned long long*)&wcol[64 * SRX + k];
        unsigned long long b3 = *(const unsigned long long*)&wcol[96 * SRX + k];
        #pragma unroll
        for (int i = 0; i < 4; i++) {
            unsigned long long a = *(const unsigned long long*)&xrow[i * SRX + k];
            acc[i][0] = fma2(a, b0, acc[i][0]);
            acc[i][1] = fma2(a, b1, acc[i][1]);
            acc[i][2] = fma2(a, b2, acc[i][2]);
            acc[i][3] = fma2(a, b3, acc[i][3]);
        }
    }
    __syncthreads();   // wt reads done; region becomes staging

    // epilogue: mask = relu(lo+hi+cterm); xc = mask*x; fp16 staged
    __half* staged = (__half*)(smem + WT_OFF);   // stride 260 halfs/row
    #pragma unroll
    for (int i = 0; i < 4; i++) {
        const int r = r0 + i;
        const float dv = dss[r];
        #pragma unroll
        for (int j = 0; j < 4; j++) {
            const int c = tx + 32 * j;
            float lo, hi;
            unpack2(acc[i][j], lo, hi);
            float m = fmaxf(lo + hi + cts[c], 0.f);
            float x0 = xs[r * SRX + c];
            float xc = m * x0;
            staged[r * 260 + c]       = __float2half(xc * dv);
            staged[r * 260 + 128 + c] = __float2half((x0 - xc) * dv);
        }
    }
    __syncthreads();
    // copy-out: 64 rows x 256 halfs (= 64 uint2/row), coalesced 8B stores
    const uint2* sg = (const uint2*)staged;      // 65 uint2 per staged row
    #pragma unroll
    for (int i = tid; i < 4096; i += 512) {
        int row = i >> 6, q = i & 63;
        ((uint2*)(g_h + (long)(node0 + row) * 256))[q] = sg[row * 65 + q];
    }
}

// ---------------- gather: warp per v, 8 graphs per block ----------------
__global__ void __launch_bounds__(256)
k_gather() {
    int w = threadIdx.x >> 5;
    int lane = threadIdx.x & 31;
    int v = blockIdx.x * 8 + w;
    if (v >= NV_) return;

    const uint4* base = (const uint4*)g_h;   // 32 uint4 per node row
    float acc[8];
    #pragma unroll
    for (int i = 0; i < 8; i++) acc[i] = 0.f;

    #pragma unroll
    for (int gg = 0; gg < 8; gg++) {
        int graph = blockIdx.y * 8 + gg;
        long node = (long)graph * N_ + v;
        float a[8], t[8];
        h8_to_f8(base[node * 32 + lane], a);     // self term
        int cnt = g_cnt[node];
        if (cnt > CAP_) cnt = CAP_;
        const int* col = g_col + node * CAP_;
        long gbase = (long)graph * N_;
        int e = 0;
        if (cnt & 1) {
            h8_to_f8(base[(gbase + col[0]) * 32 + lane], t);
            #pragma unroll
            for (int i = 0; i < 8; i++) a[i] += t[i];
            e = 1;
        }
        for (; e < cnt; e += 2) {
            long s0 = gbase + col[e];
            long s1 = gbase + col[e + 1];
            uint4 u0 = base[s0 * 32 + lane];
            uint4 u1 = base[s1 * 32 + lane];
            float t1[8];
            h8_to_f8(u0, t);
            h8_to_f8(u1, t1);
            #pragma unroll
            for (int i = 0; i < 8; i++) a[i] += t[i] + t1[i];
        }
        float dv = g_dis[node];
        #pragma unroll
        for (int i = 0; i < 8; i++) acc[i] += dv * a[i];
    }
    const float sc = 1.0f / (float)G_;
    float* dst = &g_z[v * 256 + lane * 8];
    red4(dst,     acc[0] * sc, acc[1] * sc, acc[2] * sc, acc[3] * sc);
    red4(dst + 4, acc[4] * sc, acc[5] * sc, acc[6] * sc, acc[7] * sc);
}

// ---------------- final tiny GEMM: out = z @ W + b ----------------
#define SROW 132
#define SMEM_FIN ((2 * 128 * SROW + 128) * 4)
__global__ void __launch_bounds__(512)
k_final(const float* __restrict__ W2, const float* __restrict__ b2,
        const float* __restrict__ W3, const float* __restrict__ b3,
        float* __restrict__ out) {
    extern __shared__ float sm[];
    float* zs = sm;
    float* ws = sm + 128 * SROW;
    float* bs = sm + 2 * 128 * SROW;

    const int half = blockIdx.y;       // 0 = core (W2), 1 = red (W3)
    const int rb = blockIdx.x * 128;
    const int tid = threadIdx.x;
    const float* W = half ? W3 : W2;
    const float* B = half ? b3 : b2;

    const float4* wv = (const float4*)W;
    const float4* zv = (const float4*)g_z;
    #pragma unroll
    for (int i = tid; i < 4096; i += 512) {
        int r = i >> 5, c4 = i & 31;
        *(float4*)&ws[r * SROW + c4 * 4] = wv[i];
        int rg = rb + r;
        float4 zt = make_float4(0.f, 0.f, 0.f, 0.f);
        if (rg < NV_) zt = zv[(long)rg * 64 + half * 32 + c4];
        *(float4*)&zs[r * SROW + c4 * 4] = zt;
    }
    if (tid < 128) bs[tid] = B[tid];
    __syncthreads();

    const int ty = tid >> 4, tx = tid & 15;
    const int r0 = ty * 4, c0 = tx * 8;

    unsigned long long acc[4][4];
    #pragma unroll
    for (int i = 0; i < 4; i++)
        #pragma unroll
        for (int j = 0; j < 4; j++) acc[i][j] = 0ull;

    #pragma unroll 4
    for (int k = 0; k < 128; k++) {
        double2 b01 = *(const double2*)&ws[k * SROW + c0];
        double2 b23 = *(const double2*)&ws[k * SROW + c0 + 4];
        unsigned long long bb0 = __double_as_longlong(b01.x);
        unsigned long long bb1 = __double_as_longlong(b01.y);
        unsigned long long bb2 = __double_as_longlong(b23.x);
        unsigned long long bb3 = __double_as_longlong(b23.y);
        #pragma unroll
        for (int i = 0; i < 4; i++) {
            unsigned long long ap = pack2(zs[(r0 + i) * SROW + k]);
            acc[i][0] = fma2(ap, bb0, acc[i][0]);
            acc[i][1] = fma2(ap, bb1, acc[i][1]);
            acc[i][2] = fma2(ap, bb2, acc[i][2]);
            acc[i][3] = fma2(ap, bb3, acc[i][3]);
        }
    }

    float* ob = out + (long)half * NV_ * 128;
    #pragma unroll
    for (int i = 0; i < 4; i++) {
        int rg = rb + r0 + i;
        if (rg >= NV_) continue;
        float v0, v1, v2, v3, v4, v5, v6, v7;
        unpack2(acc[i][0], v0, v1); unpack2(acc[i][1], v2, v3);
        unpack2(acc[i][2], v4, v5); unpack2(acc[i][3], v6, v7);
        float* dst = ob + (long)rg * 128 + c0;
        *(float4*)dst       = make_float4(v0 + bs[c0],     v1 + bs[c0 + 1],
                                          v2 + bs[c0 + 2], v3 + bs[c0 + 3]);
        *(float4*)(dst + 4) = make_float4(v4 + bs[c0 + 4], v5 + bs[c0 + 5],
                                          v6 + bs[c0 + 6], v7 + bs[c0 + 7]);
    }
}

// ---------------- launch ----------------
extern "C" void kernel_launch(void* const* d_in, const int* in_sizes, int n_in,
                              void* d_out, int out_size) {
    const float* x   = (const float*)d_in[0];
    const void*  ei  = d_in[1];
    const void*  cni = d_in[3];
    const float* W1  = (const float*)d_in[4];
    const float* b1  = (const float*)d_in[5];
    const float* W2  = (const float*)d_in[6];
    const float* b2  = (const float*)d_in[7];
    const float* W3  = (const float*)d_in[8];
    const float* b3  = (const float*)d_in[9];
    const float* Wm  = (const float*)d_in[10];
    const float* bm  = (const float*)d_in[11];
    float* out = (float*)d_out;

    cudaFuncSetAttribute(k_mask, cudaFuncAttributeMaxDynamicSharedMemorySize,
                         SMEM_MASK_TOTAL);
    cudaFuncSetAttribute(k_final, cudaFuncAttributeMaxDynamicSharedMemorySize,
                         SMEM_FIN);

    k_init<<<2048, 256>>>(cni, Wm);
    k_build<<<GE_ / 256, 256>>>(ei);
    k_ce_dis<<<64 + GN_ / 512, 512>>>(x, cni, W1, b1, Wm, bm);
    k_mask<<<dim3(32, 64), 512, SMEM_MASK_TOTAL>>>(x);
    k_gather<<<dim3(256, 8), 256>>>();
    k_final<<<dim3(16, 2), 512, SMEM_FIN>>>(W2, b2, W3, b3, out);
}

// round 14
// speedup vs baseline: 1.0442x; 1.0442x over previous
#include <cuda_runtime.h>
#include <cuda_fp16.h>

// Problem constants
#define G_   64
#define N_   2048
#define E_   16384
#define GE_  (G_ * E_)          // 1048576 edges total
#define NV_  2047               // nodes per graph excluding center
#define F_   128
#define GN_  (G_ * N_)          // 131072 node slots
#define CAP_ 64                 // per-node in-edge capacity (P(overflow) ~ 1e-35)

// ---------------- device scratch ----------------
// per node: 256 fp16 = [dis*xc (128) | dis*xr (128)]  (512 B/row)
__device__ __half g_h[(size_t)GN_ * 256];
__device__ float g_z[2048 * 256];            // per-v accum: [core(128) | red(128)]
__device__ int   g_cnt[GN_];
__device__ int   g_col[(size_t)GN_ * CAP_];  // local src ids
__device__ float g_dis[GN_];
__device__ float g_cterm[G_ * F_];
__device__ int   g_is64;
__device__ float g_wt[128 * 128];            // W^T of Wm bottom half: wt[c][k]

// ---------------- packed f32x2 helpers (sm_103a) ----------------
__device__ __forceinline__ unsigned long long fma2(unsigned long long a,
                                                   unsigned long long b,
                                                   unsigned long long c) {
    unsigned long long d;
    asm("fma.rn.f32x2 %0, %1, %2, %3;" : "=l"(d) : "l"(a), "l"(b), "l"(c));
    return d;
}
__device__ __forceinline__ unsigned long long pack2(float x) {
    unsigned long long d;
    asm("mov.b64 %0, {%1, %2};" : "=l"(d) : "f"(x), "f"(x));
    return d;
}
__device__ __forceinline__ void unpack2(unsigned long long v, float& lo, float& hi) {
    asm("mov.b64 {%0, %1}, %2;" : "=f"(lo), "=f"(hi) : "l"(v));
}
__device__ __forceinline__ void red4(float* p, float a, float b, float c, float d) {
    asm volatile("red.global.add.v4.f32 [%0], {%1, %2, %3, %4};"
                 :: "l"(p), "f"(a), "f"(b), "f"(c), "f"(d) : "memory");
}
__device__ __forceinline__ int edge_val(const void* ei, long idx) {
    if (g_is64) return (int)((const long long*)ei)[idx];
    return ((const int*)ei)[idx];
}
__device__ __forceinline__ void h8_to_f8(uint4 t, float* f) {
    float2 p;
    p = __half22float2(*(__half2*)&t.x); f[0] = p.x; f[1] = p.y;
    p = __half22float2(*(__half2*)&t.y); f[2] = p.x; f[3] = p.y;
    p = __half22float2(*(__half2*)&t.z); f[4] = p.x; f[5] = p.y;
    p = __half22float2(*(__half2*)&t.w); f[6] = p.x; f[7] = p.y;
}

// ---------------- init: dtype detect + zero cnt/z + W^T build ------------
__global__ void k_init(const void* cni, const float* __restrict__ Wm) {
    int i = blockIdx.x * blockDim.x + threadIdx.x;
    if (i == 0) g_is64 = (((const int*)cni)[1] == 0) ? 1 : 0;
    if (i < GN_) g_cnt[i] = 0;
    g_z[i] = 0.0f;                     // grid is exactly 2048*256 = |g_z|
    if (i < 16384) {                   // wt[c][k] = Wm[128+k][c]
        int c = i >> 7, k = i & 127;
        g_wt[c * 128 + k] = Wm[(128 + k) * 128 + c];
    }
}

// one pass: bucketed edge build
__global__ void k_build(const void* ei) {
    int e = blockIdx.x * blockDim.x + threadIdx.x;
    if (e < GE_) {
        int d = edge_val(ei, (long)GE_ + e);
        int s = edge_val(ei, e) & (N_ - 1);
        int slot = atomicAdd(&g_cnt[d], 1);
        if (slot < CAP_) g_col[(long)d * CAP_ + slot] = s;
    }
}

// merged: blocks [0,64) compute ce/cterm; blocks [64,320) compute g_dis
__global__ void __launch_bounds__(512)
k_ce_dis(const float* __restrict__ x, const void* cni,
         const float* __restrict__ W1, const float* __restrict__ b1,
         const float* __restrict__ Wm, const float* __restrict__ bm) {
    if (blockIdx.x >= 64) {
        int i = (blockIdx.x - 64) * 512 + threadIdx.x;
        if (i < GN_) g_dis[i] = rsqrtf(1.0f + (float)g_cnt[i]);
        return;
    }
    __shared__ float sx[128], sp[4][128], sce[128];
    int g = blockIdx.x, tid = threadIdx.x;
    int col = tid & 127, seg = tid >> 7;
    long center;
    if (g_is64) center = ((const long long*)cni)[g];
    else        center = ((const int*)cni)[g];
    if (tid < 128) sx[tid] = x[((long)g * N_ + center) * F_ + tid];
    __syncthreads();

    float s = 0.f;
    int k0 = seg * 32;
    #pragma unroll 32
    for (int k = 0; k < 32; k++) s += sx[k0 + k] * W1[(k0 + k) * 128 + col];
    sp[seg][col] = s;
    __syncthreads();
    if (seg == 0) sce[col] = b1[col] + sp[0][col] + sp[1][col] + sp[2][col] + sp[3][col];
    __syncthreads();

    float t = 0.f;
    #pragma unroll 32
    for (int k = 0; k < 32; k++) t += sce[k0 + k] * Wm[(k0 + k) * 128 + col];
    sp[seg][col] = t;
    __syncthreads();
    if (seg == 0)
        g_cterm[g * 128 + col] = bm[col] + sp[0][col] + sp[1][col] + sp[2][col] + sp[3][col];
}

// ---------------- mask GEMM: f32x2, LDS.128 K-quads, fma-bound -----------
// Block 128x128, 512 threads. tx = tid&31, ty = tid>>5 (0..15).
// Thread: rows ty*8..+7, cols tx+32j (j=0..3). acc[i][j] f32x2
// holds (even-k, odd-k) partials -> 32 ULL = 64 regs.
// Per 4-k quad: A = 8 LDS.128 broadcast (8 phases), B = 4 LDS.128
// conflict-free (16 phases); 64 fma2 -> P=24 < F/2=32 (fma-bound).
#define SRX 132
#define XS_OFF 0                       // 128*132*4 = 67584
#define WT_OFF 67584                   // 128*132*4 = 67584
#define CTS_OFF 135168                 // 512
#define DIS_OFF 135680                 // 512
#define SMEM_MASK_TOTAL 136192
// staged fp16 epilogue reuses WT region: 128 rows x 260 halfs = 66560 B

__global__ void __launch_bounds__(512)
k_mask(const float* __restrict__ x) {
    extern __shared__ char smem[];
    float* xs = (float*)(smem + XS_OFF);
    float* wt = (float*)(smem + WT_OFF);
    float* cts = (float*)(smem + CTS_OFF);
    float* dss = (float*)(smem + DIS_OFF);

    const int tid = threadIdx.x;
    const int g = blockIdx.y, vb = blockIdx.x;
    const int node0 = g * N_ + vb * 128;

    // fill xs (128-row x tile) and wt (128x128 W^T), 16B stores
    {
        const float4* xg = (const float4*)(x + (long)node0 * F_);
        const float4* wg = (const float4*)g_wt;
        #pragma unroll
        for (int i = tid; i < 4096; i += 512) {
            int r = i >> 5, c4 = (i & 31) * 4;
            *(float4*)&xs[r * SRX + c4] = xg[i];
            *(float4*)&wt[r * SRX + c4] = wg[i];
        }
    }
    if (tid < 128) {
        cts[tid] = g_cterm[g * 128 + tid];
        dss[tid] = g_dis[node0 + tid];
    }
    __syncthreads();

    const int tx = tid & 31, ty = tid >> 5;
    const int r0 = ty * 8;

    unsigned long long acc[8][4];
    #pragma unroll
    for (int i = 0; i < 8; i++)
        #pragma unroll
        for (int j = 0; j < 4; j++) acc[i][j] = 0ull;

    const float* xrow = xs + r0 * SRX;
    const float* wcol = wt + tx * SRX;

    #pragma unroll 2
    for (int kq = 0; kq < 32; kq++) {
        const int k = 4 * kq;
        ulonglong2 b0 = *(const ulonglong2*)&wcol[k];
        ulonglong2 b1 = *(const ulonglong2*)&wcol[32 * SRX + k];
        ulonglong2 b2 = *(const ulonglong2*)&wcol[64 * SRX + k];
        ulonglong2 b3 = *(const ulonglong2*)&wcol[96 * SRX + k];
        #pragma unroll
        for (int i = 0; i < 8; i++) {
            ulonglong2 a = *(const ulonglong2*)&xrow[i * SRX + k];
            acc[i][0] = fma2(a.x, b0.x, acc[i][0]);
            acc[i][1] = fma2(a.x, b1.x, acc[i][1]);
            acc[i][2] = fma2(a.x, b2.x, acc[i][2]);
            acc[i][3] = fma2(a.x, b3.x, acc[i][3]);
            acc[i][0] = fma2(a.y, b0.y, acc[i][0]);
            acc[i][1] = fma2(a.y, b1.y, acc[i][1]);
            acc[i][2] = fma2(a.y, b2.y, acc[i][2]);
            acc[i][3] = fma2(a.y, b3.y, acc[i][3]);
        }
    }
    __syncthreads();   // wt reads done; region becomes staging

    // epilogue: mask = relu(lo+hi+cterm); xc = mask*x; fp16 staged
    __half* staged = (__half*)(smem + WT_OFF);   // stride 260 halfs/row
    #pragma unroll
    for (int i = 0; i < 8; i++) {
        const int r = r0 + i;
        const float dv = dss[r];
        #pragma unroll
        for (int j = 0; j < 4; j++) {
            const int c = tx + 32 * j;
            float lo, hi;
            unpack2(acc[i][j], lo, hi);
            float m = fmaxf(lo + hi + cts[c], 0.f);
            float x0 = xs[r * SRX + c];
            float xc = m * x0;
            staged[r * 260 + c]       = __float2half(xc * dv);
            staged[r * 260 + 128 + c] = __float2half((x0 - xc) * dv);
        }
    }
    __syncthreads();
    // copy-out: 128 rows x 256 halfs (= 64 uint2/row), coalesced 8B stores
    const uint2* sg = (const uint2*)staged;      // 65 uint2 per staged row
    #pragma unroll
    for (int i = tid; i < 8192; i += 512) {
        int row = i >> 6, q = i & 63;
        ((uint2*)(g_h + (long)(node0 + row) * 256))[q] = sg[row * 65 + q];
    }
}

// ---------------- gather: warp per v, 8 graphs per block ----------------
__global__ void __launch_bounds__(256)
k_gather() {
    int w = threadIdx.x >> 5;
    int lane = threadIdx.x & 31;
    int v = blockIdx.x * 8 + w;
    if (v >= NV_) return;

    const uint4* base = (const uint4*)g_h;   // 32 uint4 per node row
    float acc[8];
    #pragma unroll
    for (int i = 0; i < 8; i++) acc[i] = 0.f;

    #pragma unroll
    for (int gg = 0; gg < 8; gg++) {
        int graph = blockIdx.y * 8 + gg;
        long node = (long)graph * N_ + v;
        float a[8], t[8];
        h8_to_f8(base[node * 32 + lane], a);     // self term
        int cnt = g_cnt[node];
        if (cnt > CAP_) cnt = CAP_;
        const int* col = g_col + node * CAP_;
        long gbase = (long)graph * N_;
        int e = 0;
        if (cnt & 1) {
            h8_to_f8(base[(gbase + col[0]) * 32 + lane], t);
            #pragma unroll
            for (int i = 0; i < 8; i++) a[i] += t[i];
            e = 1;
        }
        for (; e < cnt; e += 2) {
            long s0 = gbase + col[e];
            long s1 = gbase + col[e + 1];
            uint4 u0 = base[s0 * 32 + lane];
            uint4 u1 = base[s1 * 32 + lane];
            float t1[8];
            h8_to_f8(u0, t);
            h8_to_f8(u1, t1);
            #pragma unroll
            for (int i = 0; i < 8; i++) a[i] += t[i] + t1[i];
        }
        float dv = g_dis[node];
        #pragma unroll
        for (int i = 0; i < 8; i++) acc[i] += dv * a[i];
    }
    const float sc = 1.0f / (float)G_;
    float* dst = &g_z[v * 256 + lane * 8];
    red4(dst,     acc[0] * sc, acc[1] * sc, acc[2] * sc, acc[3] * sc);
    red4(dst + 4, acc[4] * sc, acc[5] * sc, acc[6] * sc, acc[7] * sc);
}

// ---------------- final tiny GEMM: out = z @ W + b ----------------
#define SROW 132
#define SMEM_FIN ((2 * 128 * SROW + 128) * 4)
__global__ void __launch_bounds__(512)
k_final(const float* __restrict__ W2, const float* __restrict__ b2,
        const float* __restrict__ W3, const float* __restrict__ b3,
        float* __restrict__ out) {
    extern __shared__ float sm[];
    float* zs = sm;
    float* ws = sm + 128 * SROW;
    float* bs = sm + 2 * 128 * SROW;

    const int half = blockIdx.y;       // 0 = core (W2), 1 = red (W3)
    const int rb = blockIdx.x * 128;
    const int tid = threadIdx.x;
    const float* W = half ? W3 : W2;
    const float* B = half ? b3 : b2;

    const float4* wv = (const float4*)W;
    const float4* zv = (const float4*)g_z;
    #pragma unroll
    for (int i = tid; i < 4096; i += 512) {
        int r = i >> 5, c4 = i & 31;
        *(float4*)&ws[r * SROW + c4 * 4] = wv[i];
        int rg = rb + r;
        float4 zt = make_float4(0.f, 0.f, 0.f, 0.f);
        if (rg < NV_) zt = zv[(long)rg * 64 + half * 32 + c4];
        *(float4*)&zs[r * SROW + c4 * 4] = zt;
    }
    if (tid < 128) bs[tid] = B[tid];
    __syncthreads();

    const int ty = tid >> 4, tx = tid & 15;
    const int r0 = ty * 4, c0 = tx * 8;

    unsigned long long acc[4][4];
    #pragma unroll
    for (int i = 0; i < 4; i++)
        #pragma unroll
        for (int j = 0; j < 4; j++) acc[i][j] = 0ull;

    #pragma unroll 4
    for (int k = 0; k < 128; k++) {
        double2 b01 = *(const double2*)&ws[k * SROW + c0];
        double2 b23 = *(const double2*)&ws[k * SROW + c0 + 4];
        unsigned long long bb0 = __double_as_longlong(b01.x);
        unsigned long long bb1 = __double_as_longlong(b01.y);
        unsigned long long bb2 = __double_as_longlong(b23.x);
        unsigned long long bb3 = __double_as_longlong(b23.y);
        #pragma unroll
        for (int i = 0; i < 4; i++) {
            unsigned long long ap = pack2(zs[(r0 + i) * SROW + k]);
            acc[i][0] = fma2(ap, bb0, acc[i][0]);
            acc[i][1] = fma2(ap, bb1, acc[i][1]);
            acc[i][2] = fma2(ap, bb2, acc[i][2]);
            acc[i][3] = fma2(ap, bb3, acc[i][3]);
        }
    }

    float* ob = out + (long)half * NV_ * 128;
    #pragma unroll
    for (int i = 0; i < 4; i++) {
        int rg = rb + r0 + i;
        if (rg >= NV_) continue;
        float v0, v1, v2, v3, v4, v5, v6, v7;
        unpack2(acc[i][0], v0, v1); unpack2(acc[i][1], v2, v3);
        unpack2(acc[i][2], v4, v5); unpack2(acc[i][3], v6, v7);
        float* dst = ob + (long)rg * 128 + c0;
        *(float4*)dst       = make_float4(v0 + bs[c0],     v1 + bs[c0 + 1],
                                          v2 + bs[c0 + 2], v3 + bs[c0 + 3]);
        *(float4*)(dst + 4) = make_float4(v4 + bs[c0 + 4], v5 + bs[c0 + 5],
                                          v6 + bs[c0 + 6], v7 + bs[c0 + 7]);
    }
}

// ---------------- launch ----------------
extern "C" void kernel_launch(void* const* d_in, const int* in_sizes, int n_in,
                              void* d_out, int out_size) {
    const float* x   = (const float*)d_in[0];
    const void*  ei  = d_in[1];
    const void*  cni = d_in[3];
    const float* W1  = (const float*)d_in[4];
    const float* b1  = (const float*)d_in[5];
    const float* W2  = (const float*)d_in[6];
    const float* b2  = (const float*)d_in[7];
    const float* W3  = (const float*)d_in[8];
    const float* b3  = (const float*)d_in[9];
    const float* Wm  = (const float*)d_in[10];
    const float* bm  = (const float*)d_in[11];
    float* out = (float*)d_out;

    cudaFuncSetAttribute(k_mask, cudaFuncAttributeMaxDynamicSharedMemorySize,
                         SMEM_MASK_TOTAL);
    cudaFuncSetAttribute(k_final, cudaFuncAttributeMaxDynamicSharedMemorySize,
                         SMEM_FIN);

    k_init<<<2048, 256>>>(cni, Wm);
    k_build<<<GE_ / 256, 256>>>(ei);
    k_ce_dis<<<64 + GN_ / 512, 512>>>(x, cni, W1, b1, Wm, bm);
    k_mask<<<dim3(16, 64), 512, SMEM_MASK_TOTAL>>>(x);
    k_gather<<<dim3(256, 8), 256>>>();
    k_final<<<dim3(16, 2), 512, SMEM_FIN>>>(W2, b2, W3, b3, out);
}

// round 17
// speedup vs baseline: 1.1027x; 1.0561x over previous
#include <cuda_runtime.h>
#include <cuda_fp16.h>

// Problem constants
#define G_   64
#define N_   2048
#define E_   16384
#define GE_  (G_ * E_)          // 1048576 edges total
#define NV_  2047               // nodes per graph excluding center
#define F_   128
#define GN_  (G_ * N_)          // 131072 node slots
#define CAP_ 64                 // per-node in-edge capacity (P(overflow) ~ 1e-35)

// ---------------- device scratch ----------------
// per node: 256 fp16 = [dis*xc (128) | dis*xr (128)]  (512 B/row)
__device__ __half g_h[(size_t)GN_ * 256];
__device__ float g_z[2048 * 256];            // per-v accum: [core(128) | red(128)]
__device__ int   g_cnt[GN_];
__device__ int   g_col[(size_t)GN_ * CAP_];  // local src ids
__device__ float g_dis[GN_];
__device__ float g_cterm[G_ * F_];
__device__ int   g_is64;

// ---------------- packed f32x2 helpers (sm_103a) ----------------
__device__ __forceinline__ unsigned long long fma2(unsigned long long a,
                                                   unsigned long long b,
                                                   unsigned long long c) {
    unsigned long long d;
    asm("fma.rn.f32x2 %0, %1, %2, %3;" : "=l"(d) : "l"(a), "l"(b), "l"(c));
    return d;
}
__device__ __forceinline__ unsigned long long pack2(float x) {
    unsigned long long d;
    asm("mov.b64 %0, {%1, %2};" : "=l"(d) : "f"(x), "f"(x));
    return d;
}
__device__ __forceinline__ void unpack2(unsigned long long v, float& lo, float& hi) {
    asm("mov.b64 {%0, %1}, %2;" : "=f"(lo), "=f"(hi) : "l"(v));
}
__device__ __forceinline__ void red4(float* p, float a, float b, float c, float d) {
    asm volatile("red.global.add.v4.f32 [%0], {%1, %2, %3, %4};"
                 :: "l"(p), "f"(a), "f"(b), "f"(c), "f"(d) : "memory");
}
__device__ __forceinline__ int edge_val(const void* ei, long idx) {
    if (g_is64) return (int)((const long long*)ei)[idx];
    return ((const int*)ei)[idx];
}
__device__ __forceinline__ void h8_to_f8(uint4 t, float* f) {
    float2 p;
    p = __half22float2(*(__half2*)&t.x); f[0] = p.x; f[1] = p.y;
    p = __half22float2(*(__half2*)&t.y); f[2] = p.x; f[3] = p.y;
    p = __half22float2(*(__half2*)&t.z); f[4] = p.x; f[5] = p.y;
    p = __half22float2(*(__half2*)&t.w); f[6] = p.x; f[7] = p.y;
}
// 4 floats -> 4 fp16 (uint2)
__device__ __forceinline__ uint2 f4_to_h4(float a, float b, float c, float d) {
    uint2 t;
    *(__half2*)&t.x = __floats2half2_rn(a, b);
    *(__half2*)&t.y = __floats2half2_rn(c, d);
    return t;
}

// ---------------- init: dtype detect + zero cnt + zero z ----------------
__global__ void k_init(const void* cni) {
    int i = blockIdx.x * blockDim.x + threadIdx.x;
    if (i == 0) g_is64 = (((const int*)cni)[1] == 0) ? 1 : 0;
    if (i < GN_) g_cnt[i] = 0;
    if (i < 2048 * 256) g_z[i] = 0.0f;
}

// bucketed edge build: 2 edges per thread, paired 16B/8B index loads
__global__ void k_build(const void* ei) {
    int t = blockIdx.x * blockDim.x + threadIdx.x;
    if (t < GE_ / 2) {
        int d0, d1, s0, s1;
        if (g_is64) {
            longlong2 dd = ((const longlong2*)ei)[(GE_ / 2) + t];
            longlong2 ss = ((const longlong2*)ei)[t];
            d0 = (int)dd.x; d1 = (int)dd.y;
            s0 = (int)ss.x; s1 = (int)ss.y;
        } else {
            int2 dd = ((const int2*)ei)[(GE_ / 2) + t];
            int2 ss = ((const int2*)ei)[t];
            d0 = dd.x; d1 = dd.y; s0 = ss.x; s1 = ss.y;
        }
        int slot0 = atomicAdd(&g_cnt[d0], 1);
        if (slot0 < CAP_) g_col[(long)d0 * CAP_ + slot0] = s0 & (N_ - 1);
        int slot1 = atomicAdd(&g_cnt[d1], 1);
        if (slot1 < CAP_) g_col[(long)d1 * CAP_ + slot1] = s1 & (N_ - 1);
    }
}

// merged: blocks [0,64) compute ce/cterm; blocks [64,320) compute g_dis
__global__ void __launch_bounds__(512)
k_ce_dis(const float* __restrict__ x, const void* cni,
         const float* __restrict__ W1, const float* __restrict__ b1,
         const float* __restrict__ Wm, const float* __restrict__ bm) {
    if (blockIdx.x >= 64) {
        int i = (blockIdx.x - 64) * 512 + threadIdx.x;
        if (i < GN_) g_dis[i] = rsqrtf(1.0f + (float)g_cnt[i]);
        return;
    }
    __shared__ float sx[128], sp[4][128], sce[128];
    int g = blockIdx.x, tid = threadIdx.x;
    int col = tid & 127, seg = tid >> 7;
    long center;
    if (g_is64) center = ((const long long*)cni)[g];
    else        center = ((const int*)cni)[g];
    if (tid < 128) sx[tid] = x[((long)g * N_ + center) * F_ + tid];
    __syncthreads();

    float s = 0.f;
    int k0 = seg * 32;
    #pragma unroll 32
    for (int k = 0; k < 32; k++) s += sx[k0 + k] * W1[(k0 + k) * 128 + col];
    sp[seg][col] = s;
    __syncthreads();
    if (seg == 0) sce[col] = b1[col] + sp[0][col] + sp[1][col] + sp[2][col] + sp[3][col];
    __syncthreads();

    float t = 0.f;
    #pragma unroll 32
    for (int k = 0; k < 32; k++) t += sce[k0 + k] * Wm[(k0 + k) * 128 + col];
    sp[seg][col] = t;
    __syncthreads();
    if (seg == 0)
        g_cterm[g * 128 + col] = bm[col] + sp[0][col] + sp[1][col] + sp[2][col] + sp[3][col];
}

// ---------------- mask GEMM + epilogue (R6 best-measured variant) --------
// Block: 128 rows x 128 cols, 256 threads (16x16), 8 rows x (4+4) cols each.
// Thread (ty, tx): rows ty*8..+7, cols {tx*4..+3} and {64+tx*4..+3}.
#define SROW 132
#define SMEM_MASK ((2 * 128 * SROW + 128) * 4)

__global__ void __launch_bounds__(256)
k_mask(const float* __restrict__ x, const float* __restrict__ Wm) {
    extern __shared__ float sm[];
    float* xs  = sm;                     // x tile
    float* ws  = sm + 128 * SROW;        // Wm bottom half
    float* cts = sm + 2 * 128 * SROW;    // per-col center term

    const int g = blockIdx.y, vb = blockIdx.x;
    const int node0 = g * N_ + vb * 128;
    const int tid = threadIdx.x;

    const float4* xg = (const float4*)(x + (long)node0 * F_);
    const float4* wmB = (const float4*)(Wm + 128 * 128);
    #pragma unroll
    for (int i = tid; i < 4096; i += 256) {
        int r = i >> 5, c4 = i & 31;
        *(float4*)&xs[r * SROW + c4 * 4] = xg[i];
        *(float4*)&ws[r * SROW + c4 * 4] = wmB[i];
    }
    if (tid < 128) cts[tid] = g_cterm[g * 128 + tid];
    __syncthreads();

    const int ty = tid >> 4, tx = tid & 15;
    const int r0 = ty * 8;
    const int ca = tx * 4;           // cols ca..ca+3
    const int cb = 64 + tx * 4;      // cols cb..cb+3

    unsigned long long acc[8][4];    // [row][0..1]=colsA, [2..3]=colsB
    #pragma unroll
    for (int i = 0; i < 8; i++)
        #pragma unroll
        for (int j = 0; j < 4; j++) acc[i][j] = 0ull;

    #pragma unroll 2
    for (int k = 0; k < 128; k++) {
        double2 bA = *(const double2*)&ws[k * SROW + ca];
        double2 bB = *(const double2*)&ws[k * SROW + cb];
        unsigned long long b0 = __double_as_longlong(bA.x);
        unsigned long long b1 = __double_as_longlong(bA.y);
        unsigned long long b2 = __double_as_longlong(bB.x);
        unsigned long long b3 = __double_as_longlong(bB.y);
        #pragma unroll
        for (int i = 0; i < 8; i++) {
            unsigned long long ap = pack2(xs[(r0 + i) * SROW + k]);
            acc[i][0] = fma2(ap, b0, acc[i][0]);
            acc[i][1] = fma2(ap, b1, acc[i][1]);
            acc[i][2] = fma2(ap, b2, acc[i][2]);
            acc[i][3] = fma2(ap, b3, acc[i][3]);
        }
    }

    // epilogue: xc = relu(mask)*x; store fp16 dis-scaled xc and xr = x - xc
    #pragma unroll
    for (int i = 0; i < 8; i++) {
        int r = r0 + i;
        float dv = g_dis[node0 + r];
        __half* row = g_h + (long)(node0 + r) * 256;
        #pragma unroll
        for (int half = 0; half < 2; half++) {
            int c = half ? cb : ca;
            float m0, m1, m2, m3;
            unpack2(acc[i][2 * half],     m0, m1);
            unpack2(acc[i][2 * half + 1], m2, m3);
            m0 = fmaxf(m0 + cts[c], 0.f);
            m1 = fmaxf(m1 + cts[c + 1], 0.f);
            m2 = fmaxf(m2 + cts[c + 2], 0.f);
            m3 = fmaxf(m3 + cts[c + 3], 0.f);
            float x0 = xs[r * SROW + c],     x1 = xs[r * SROW + c + 1];
            float x2 = xs[r * SROW + c + 2], x3 = xs[r * SROW + c + 3];
            float c0 = m0 * x0, c1 = m1 * x1, c2 = m2 * x2, c3 = m3 * x3;
            *(uint2*)(row + c) =
                f4_to_h4(c0 * dv, c1 * dv, c2 * dv, c3 * dv);
            *(uint2*)(row + 128 + c) =
                f4_to_h4((x0 - c0) * dv, (x1 - c1) * dv,
                         (x2 - c2) * dv, (x3 - c3) * dv);
        }
    }
}

// ---------------- gather: warp per v, 8 graphs per block ----------------
__global__ void __launch_bounds__(256)
k_gather() {
    int w = threadIdx.x >> 5;
    int lane = threadIdx.x & 31;
    int v = blockIdx.x * 8 + w;
    if (v >= NV_) return;

    const uint4* base = (const uint4*)g_h;   // 32 uint4 per node row
    float acc[8];
    #pragma unroll
    for (int i = 0; i < 8; i++) acc[i] = 0.f;

    #pragma unroll
    for (int gg = 0; gg < 8; gg++) {
        int graph = blockIdx.y * 8 + gg;
        long node = (long)graph * N_ + v;
        float a[8], t[8];
        h8_to_f8(base[node * 32 + lane], a);     // self term
        int cnt = g_cnt[node];
        if (cnt > CAP_) cnt = CAP_;
        const int* col = g_col + node * CAP_;
        long gbase = (long)graph * N_;
        int e = 0;
        if (cnt & 1) {
            h8_to_f8(base[(gbase + col[0]) * 32 + lane], t);
            #pragma unroll
            for (int i = 0; i < 8; i++) a[i] += t[i];
            e = 1;
        }
        for (; e < cnt; e += 2) {
            long s0 = gbase + col[e];
            long s1 = gbase + col[e + 1];
            uint4 u0 = base[s0 * 32 + lane];
            uint4 u1 = base[s1 * 32 + lane];
            float t1[8];
            h8_to_f8(u0, t);
            h8_to_f8(u1, t1);
            #pragma unroll
            for (int i = 0; i < 8; i++) a[i] += t[i] + t1[i];
        }
        float dv = g_dis[node];
        #pragma unroll
        for (int i = 0; i < 8; i++) acc[i] += dv * a[i];
    }
    const float sc = 1.0f / (float)G_;
    float* dst = &g_z[v * 256 + lane * 8];
    red4(dst,     acc[0] * sc, acc[1] * sc, acc[2] * sc, acc[3] * sc);
    red4(dst + 4, acc[4] * sc, acc[5] * sc, acc[6] * sc, acc[7] * sc);
}

// ---------------- final tiny GEMM: out = z @ W + b (64-row blocks) -------
#define SMEM_FIN ((192 * SROW + 128) * 4)
__global__ void __launch_bounds__(512)
k_final(const float* __restrict__ W2, const float* __restrict__ b2,
        const float* __restrict__ W3, const float* __restrict__ b3,
        float* __restrict__ out) {
    extern __shared__ float sm[];
    float* zs = sm;                      // 64 x SROW
    float* ws = sm + 64 * SROW;          // 128 x SROW
    float* bs = sm + 192 * SROW;

    const int half = blockIdx.y;       // 0 = core (W2), 1 = red (W3)
    const int rb = blockIdx.x * 64;
    const int tid = threadIdx.x;
    const float* W = half ? W3 : W2;
    const float* B = half ? b3 : b2;

    const float4* wv = (const float4*)W;
    const float4* zv = (const float4*)g_z;
    #pragma unroll
    for (int i = tid; i < 4096; i += 512) {
        int r = i >> 5, c4 = i & 31;
        *(float4*)&ws[r * SROW + c4 * 4] = wv[i];
        if (i < 2048) {
            int rg = rb + r;
            float4 zt = make_float4(0.f, 0.f, 0.f, 0.f);
            if (rg < NV_) zt = zv[(long)rg * 64 + half * 32 + c4];
            *(float4*)&zs[r * SROW + c4 * 4] = zt;
        }
    }
    if (tid < 128) bs[tid] = B[tid];
    __syncthreads();

    const int ty = tid >> 4, tx = tid & 15;   // ty 0..31, tx 0..15
    const int r0 = ty * 2, c0 = tx * 8;

    unsigned long long acc[2][4];
    #pragma unroll
    for (int i = 0; i < 2; i++)
        #pragma unroll
        for (int j = 0; j < 4; j++) acc[i][j] = 0ull;

    #pragma unroll 4
    for (int k = 0; k < 128; k++) {
        double2 b01 = *(const double2*)&ws[k * SROW + c0];
        double2 b23 = *(const double2*)&ws[k * SROW + c0 + 4];
        unsigned long long bb0 = __double_as_longlong(b01.x);
        unsigned long long bb1 = __double_as_longlong(b01.y);
        unsigned long long bb2 = __double_as_longlong(b23.x);
        unsigned long long bb3 = __double_as_longlong(b23.y);
        #pragma unroll
        for (int i = 0; i < 2; i++) {
            unsigned long long ap = pack2(zs[(r0 + i) * SROW + k]);
            acc[i][0] = fma2(ap, bb0, acc[i][0]);
            acc[i][1] = fma2(ap, bb1, acc[i][1]);
            acc[i][2] = fma2(ap, bb2, acc[i][2]);
            acc[i][3] = fma2(ap, bb3, acc[i][3]);
        }
    }

    float* ob = out + (long)half * NV_ * 128;
    #pragma unroll
    for (int i = 0; i < 2; i++) {
        int rg = rb + r0 + i;
        if (rg >= NV_) continue;
        float v0, v1, v2, v3, v4, v5, v6, v7;
        unpack2(acc[i][0], v0, v1); unpack2(acc[i][1], v2, v3);
        unpack2(acc[i][2], v4, v5); unpack2(acc[i][3], v6, v7);
        float* dst = ob + (long)rg * 128 + c0;
        *(float4*)dst       = make_float4(v0 + bs[c0],     v1 + bs[c0 + 1],
                                          v2 + bs[c0 + 2], v3 + bs[c0 + 3]);
        *(float4*)(dst + 4) = make_float4(v4 + bs[c0 + 4], v5 + bs[c0 + 5],
                                          v6 + bs[c0 + 6], v7 + bs[c0 + 7]);
    }
}

// ---------------- launch ----------------
extern "C" void kernel_launch(void* const* d_in, const int* in_sizes, int n_in,
                              void* d_out, int out_size) {
    const float* x   = (const float*)d_in[0];
    const void*  ei  = d_in[1];
    const void*  cni = d_in[3];
    const float* W1  = (const float*)d_in[4];
    const float* b1  = (const float*)d_in[5];
    const float* W2  = (const float*)d_in[6];
    const float* b2  = (const float*)d_in[7];
    const float* W3  = (const float*)d_in[8];
    const float* b3  = (const float*)d_in[9];
    const float* Wm  = (const float*)d_in[10];
    const float* bm  = (const float*)d_in[11];
    float* out = (float*)d_out;

    cudaFuncSetAttribute(k_mask, cudaFuncAttributeMaxDynamicSharedMemorySize,
                         SMEM_MASK);
    cudaFuncSetAttribute(k_final, cudaFuncAttributeMaxDynamicSharedMemorySize,
                         SMEM_FIN);

    k_init<<<2048, 256>>>(cni);
    k_build<<<GE_ / 512, 256>>>(ei);
    k_ce_dis<<<64 + GN_ / 512, 512>>>(x, cni, W1, b1, Wm, bm);
    k_mask<<<dim3(16, 64), 256, SMEM_MASK>>>(x, Wm);
    k_gather<<<dim3(256, 8), 256>>>();
    k_final<<<dim3(32, 2), 512, SMEM_FIN>>>(W2, b2, W3, b3, out);
}